// round 16
// baseline (speedup 1.0000x reference)
#include <cuda_runtime.h>
#include <cuda_bf16.h>
#include <cstdint>

// ---------------------------------------------------------------------------
// CrossAtt for GB300 — round 16: kv GEMM split into k-half and v-half so the
// k-chain starts ~270us earlier and overlaps the v-half GEMM.
//  A : cvt -> kGEMM -> k-chain -> softstats -> [evVh] ktv -> [evV,evQ] eff
//      -> [evP1] proj[K 0:512] +=
//  sB: q-chain -> [evVloc] ln2 -> proj[K 512:640] (+bias) -> evP1
//  sC: [evK] vGEMM -> v-chain (-> evVh) -> vloc (-> evVloc) -> crpe -> evV
// ---------------------------------------------------------------------------

#define RSQ_BN 0.9999950000374997f
#define SCALE_V 0.11180339887498949f
#define LN_EPS 1e-5f

__device__ __forceinline__ float hsw(float x) {
    return x * fminf(fmaxf(x + 3.f, 0.f), 6.f) * (1.f / 6.f);
}

__device__ __forceinline__ uint32_t smem_u32(const void* p) {
    uint32_t a;
    asm("{ .reg .u64 t; cvta.to.shared.u64 t, %1; cvt.u32.u64 %0, t; }"
        : "=r"(a) : "l"(p));
    return a;
}
__device__ __forceinline__ void cp16(uint32_t s, const void* g) {
    asm volatile("cp.async.cg.shared.global [%0], [%1], 16;" :: "r"(s), "l"(g));
}
__device__ __forceinline__ void ldm_x4(uint32_t& r0, uint32_t& r1,
                                       uint32_t& r2, uint32_t& r3, uint32_t a) {
    asm volatile("ldmatrix.sync.aligned.m8n8.x4.shared.b16 {%0,%1,%2,%3}, [%4];"
        : "=r"(r0), "=r"(r1), "=r"(r2), "=r"(r3) : "r"(a));
}
__device__ __forceinline__ void mma_bf16(float* d, const uint32_t* a, const uint32_t* b) {
    asm volatile(
        "mma.sync.aligned.m16n8k16.row.col.f32.bf16.bf16.f32 "
        "{%0,%1,%2,%3},{%4,%5,%6,%7},{%8,%9},{%0,%1,%2,%3};"
        : "+f"(d[0]), "+f"(d[1]), "+f"(d[2]), "+f"(d[3])
        : "r"(a[0]), "r"(a[1]), "r"(a[2]), "r"(a[3]), "r"(b[0]), "r"(b[1]));
}
__device__ __forceinline__ void split_bf16(float v, __nv_bfloat16& h, __nv_bfloat16& l) {
    h = __float2bfloat16(v);
    l = __float2bfloat16(v - __bfloat162float(h));
}

// ---------------- scratch ----------------------------------------------------
static __device__ __align__(256) float g_scratch[186179584ULL];

// ---------------------------------------------------------------------------
__global__ void cvt_k(const float* __restrict__ s, __nv_bfloat16* __restrict__ hi,
                      __nv_bfloat16* __restrict__ lo, long n)
{
    long i = ((long)blockIdx.x * blockDim.x + threadIdx.x) * 4;
    if (i >= n) return;
    float4 v = *reinterpret_cast<const float4*>(s + i);
    float a[4] = {v.x, v.y, v.z, v.w};
    __nv_bfloat16 h[4], l[4];
#pragma unroll
    for (int j = 0; j < 4; j++) split_bf16(a[j], h[j], l[j]);
    *reinterpret_cast<__nv_bfloat162*>(hi + i)     = __nv_bfloat162(h[0], h[1]);
    *reinterpret_cast<__nv_bfloat162*>(hi + i + 2) = __nv_bfloat162(h[2], h[3]);
    *reinterpret_cast<__nv_bfloat162*>(lo + i)     = __nv_bfloat162(l[0], l[1]);
    *reinterpret_cast<__nv_bfloat162*>(lo + i + 2) = __nv_bfloat162(l[2], l[3]);
}

// ---------------------------------------------------------------------------
// MMA GEMM: 128x128 block, 8 warps, k16 stages, shared hi/lo tiles,
// 4-stage cp.async pipeline, 2 CTAs/SM. lda/ldb row strides (>= K).
// MODE 0: C=acc  1: C=acc+p2[n]  2: BN+hswish head-scatter  3: C+=acc
// ---------------------------------------------------------------------------
#define MG_SMEM 98304

template <int MODE>
__global__ void __launch_bounds__(256, 2) mgemm_k(
    const __nv_bfloat16* __restrict__ Ahi, const __nv_bfloat16* __restrict__ Alo,
    const __nv_bfloat16* __restrict__ Bhi, const __nv_bfloat16* __restrict__ Blo,
    float* __restrict__ C, int ldc, int K, int lda, int ldb,
    const float* __restrict__ p1, const float* __restrict__ p2, int headBase)
{
    extern __shared__ __align__(16) char smem[];
    const uint32_t sbase = smem_u32(smem);

    const int tid = threadIdx.x;
    const int wid = tid >> 5, lane = tid & 31;
    const int warp_m = wid >> 2, warp_n = wid & 3;
    const int m0 = blockIdx.y * 128, n0 = blockIdx.x * 128;

    const int SC = K >> 4;

    const int row = tid >> 1, half = tid & 1;
    const uint32_t soff = (uint32_t)(row * 48 + half * 16);
    const long aRow = (long)(m0 + row) * lda + half * 8;
    const long bRow = (long)(n0 + row) * ldb + half * 8;

    float acc[4][4][4] = {};

    const uint32_t aLdm = (uint32_t)((warp_m * 64 + (lane & 15)) * 48 + (lane >> 4) * 16);
    const uint32_t bLdm = (uint32_t)((warp_n * 32 + (lane & 15)) * 48 + (lane >> 4) * 16);

#define ST_BASE(st) (sbase + (uint32_t)(st) * 24576u)
#define ISSUE(s, st)                                                           \
    {                                                                          \
        const int ko = (s) << 4;                                               \
        const uint32_t sb = ST_BASE(st);                                       \
        cp16(sb + soff,          Ahi + aRow + ko);                             \
        cp16(sb + 6144u + soff,  Alo + aRow + ko);                             \
        cp16(sb + 12288u + soff, Bhi + bRow + ko);                             \
        cp16(sb + 18432u + soff, Blo + bRow + ko);                             \
        asm volatile("cp.async.commit_group;" ::: "memory");                   \
    }

    ISSUE(0, 0);
    ISSUE(1, 1);
    ISSUE(2, 2);

    for (int s = 0; s < SC; s++) {
        const int st = s & 3;
        if (s + 2 < SC) {
            asm volatile("cp.async.wait_group 2;" ::: "memory");
        } else if (s + 1 < SC) {
            asm volatile("cp.async.wait_group 1;" ::: "memory");
        } else {
            asm volatile("cp.async.wait_group 0;" ::: "memory");
        }
        __syncthreads();

        const uint32_t sb = ST_BASE(st);

        uint32_t bh[4][2], bl[4][2];
#pragma unroll
        for (int bi = 0; bi < 2; bi++) {
            uint32_t q0, q1, q2, q3;
            ldm_x4(q0, q1, q2, q3, sb + 12288u + bLdm + bi * 768u);
            bh[bi * 2 + 0][0] = q0; bh[bi * 2 + 0][1] = q2;
            bh[bi * 2 + 1][0] = q1; bh[bi * 2 + 1][1] = q3;
            ldm_x4(q0, q1, q2, q3, sb + 18432u + bLdm + bi * 768u);
            bl[bi * 2 + 0][0] = q0; bl[bi * 2 + 0][1] = q2;
            bl[bi * 2 + 1][0] = q1; bl[bi * 2 + 1][1] = q3;
        }
#pragma unroll
        for (int mf = 0; mf < 4; mf++) {
            uint32_t a[4];
            ldm_x4(a[0], a[1], a[2], a[3], sb + aLdm + mf * 768u);
#pragma unroll
            for (int nf = 0; nf < 4; nf++) {
                mma_bf16(acc[mf][nf], a, bh[nf]);
                mma_bf16(acc[mf][nf], a, bl[nf]);
            }
        }
#pragma unroll
        for (int mf = 0; mf < 4; mf++) {
            uint32_t a[4];
            ldm_x4(a[0], a[1], a[2], a[3], sb + 6144u + aLdm + mf * 768u);
#pragma unroll
            for (int nf = 0; nf < 4; nf++)
                mma_bf16(acc[mf][nf], a, bh[nf]);
        }
        if (s + 3 < SC) ISSUE(s + 3, (s + 3) & 3);
    }
#undef ISSUE
#undef ST_BASE

    const int lr = lane >> 2;
    const int lc = (lane & 3) * 2;
#pragma unroll
    for (int mf = 0; mf < 4; mf++) {
#pragma unroll
        for (int nf = 0; nf < 4; nf++) {
            const int n = n0 + warp_n * 32 + nf * 8 + lc;
#pragma unroll
            for (int h2 = 0; h2 < 2; h2++) {
                const int m = m0 + warp_m * 64 + mf * 16 + lr + h2 * 8;
                float v0 = acc[mf][nf][2 * h2 + 0];
                float v1 = acc[mf][nf][2 * h2 + 1];
                if (MODE == 0) {
                    *reinterpret_cast<float2*>(&C[(long)m * ldc + n]) =
                        make_float2(v0, v1);
                } else if (MODE == 1) {
                    *reinterpret_cast<float2*>(&C[(long)m * ldc + n]) =
                        make_float2(v0 + p2[n], v1 + p2[n + 1]);
                } else if (MODE == 3) {
                    float2 prev = *reinterpret_cast<const float2*>(&C[(long)m * ldc + n]);
                    *reinterpret_cast<float2*>(&C[(long)m * ldc + n]) =
                        make_float2(v0 + prev.x, v1 + prev.y);
                } else {
                    v0 = hsw(v0 * (p1[n] * RSQ_BN) + p2[n]);
                    v1 = hsw(v1 * (p1[n + 1] * RSQ_BN) + p2[n + 1]);
                    const int bb = m >> 12, nn = m & 4095;
                    const int hh = headBase + (n >> 6), cc = n & 63;
                    *reinterpret_cast<float2*>(
                        &C[((((long)bb * 8 + hh) * 4096) + nn) * 64 + cc]) =
                        make_float2(v0, v1);
                }
            }
        }
    }
}

// ---------------------------------------------------------------------------
__global__ void seg0_k(const float* __restrict__ in, int inRow,
                       float* __restrict__ hb,
                       const float* __restrict__ g, const float* __restrict__ bb)
{
    const int c = threadIdx.x;
    const int n = blockIdx.x * blockDim.y + threadIdx.y;
    const int b = blockIdx.y;
    float v = in[((long)b * 4096 + n) * (long)inRow + c];
    v = v * (g[c] * RSQ_BN) + bb[c];
    v = hsw(v);
    const int h = c >> 6, cc = c & 63;
    hb[(((long)b * 8 + h) * 4096 + n) * 64 + cc] = v;
}

// ---------------------------------------------------------------------------
template <int KS, int C, int BF>
__global__ void dwconv4_k(const float* __restrict__ in, long inOuter, long inInner,
                          int inRow,
                          float* __restrict__ out,
                          __nv_bfloat16* __restrict__ ohi, __nv_bfloat16* __restrict__ olo,
                          long outOuter, long outInner,
                          const float* __restrict__ w, int nh)
{
    extern __shared__ float ws[];
    const int batch = blockIdx.y;
    const int outer = batch / nh, inner = batch % nh;
    const float* ip = in + outer * inOuter + inner * inInner;
    const float* wp = w + (long)inner * C * KS * KS;

    const int nthr = blockDim.x * blockDim.y;
    const int tid = threadIdx.y * blockDim.x + threadIdx.x;
    for (int i = tid; i < C * KS * KS; i += nthr) {
        const int c = i / (KS * KS);
        const int t = i - c * (KS * KS);
        ws[t * C + c] = wp[i];
    }
    __syncthreads();

    const int c0 = threadIdx.x * 4;
    const int pix = blockIdx.x * blockDim.y + threadIdx.y;
    const int y = pix >> 6, x = pix & 63;
    const int P = KS / 2;
    float4 acc = make_float4(0.f, 0.f, 0.f, 0.f);
#pragma unroll
    for (int dy = 0; dy < KS; dy++) {
        const int yy = y + dy - P;
        if (yy < 0 || yy > 63) continue;
#pragma unroll
        for (int dx = 0; dx < KS; dx++) {
            const int xx = x + dx - P;
            if (xx < 0 || xx > 63) continue;
            const float4 wv = *reinterpret_cast<const float4*>(
                &ws[(dy * KS + dx) * C + c0]);
            const float4 iv = *reinterpret_cast<const float4*>(
                &ip[(long)(yy * 64 + xx) * inRow + c0]);
            acc.x = fmaf(wv.x, iv.x, acc.x);
            acc.y = fmaf(wv.y, iv.y, acc.y);
            acc.z = fmaf(wv.z, iv.z, acc.z);
            acc.w = fmaf(wv.w, iv.w, acc.w);
        }
    }
    const long obase = outer * outOuter + inner * outInner + (long)pix * C + c0;
    if (BF == 0) {
        *reinterpret_cast<float4*>(&out[obase]) = acc;
    } else {
        float a[4] = {acc.x, acc.y, acc.z, acc.w};
        __nv_bfloat16 h[4], l[4];
#pragma unroll
        for (int i = 0; i < 4; i++) split_bf16(a[i], h[i], l[i]);
        *reinterpret_cast<__nv_bfloat162*>(&ohi[obase])     = __nv_bfloat162(h[0], h[1]);
        *reinterpret_cast<__nv_bfloat162*>(&ohi[obase + 2]) = __nv_bfloat162(h[2], h[3]);
        *reinterpret_cast<__nv_bfloat162*>(&olo[obase])     = __nv_bfloat162(l[0], l[1]);
        *reinterpret_cast<__nv_bfloat162*>(&olo[obase + 2]) = __nv_bfloat162(l[2], l[3]);
    }
}

// ---------------------------------------------------------------------------
__global__ void softstats_k(const float* __restrict__ Kh,
                            float* __restrict__ mx, float* __restrict__ sm,
                            float* __restrict__ ktv)
{
    const int bh = blockIdx.x;
    const int c  = threadIdx.x & 63;
    const int sl = threadIdx.x >> 6;
    const float* kp = Kh + (long)bh * 4096 * 64;

    float* kz = ktv + (long)bh * 4096;
    for (int i = threadIdx.x; i < 4096; i += 512) kz[i] = 0.f;

    float m = -1e30f;
    for (int j = 0; j < 512; j++) {
        const int n = sl * 512 + j;
        m = fmaxf(m, kp[(long)n * 64 + c]);
    }
    __shared__ float red[512];
    __shared__ float red2[512];
    red[threadIdx.x] = m;
    __syncthreads();
    if (sl == 0) {
        for (int s = 1; s < 8; s++) m = fmaxf(m, red[s * 64 + c]);
        red[c] = m;
    }
    __syncthreads();
    m = red[c];

    float s = 0.f;
    for (int j = 0; j < 512; j++) {
        const int n = sl * 512 + j;
        s += __expf(kp[(long)n * 64 + c] - m);
    }
    red2[threadIdx.x] = s;
    __syncthreads();
    if (sl == 0) {
        for (int ss = 1; ss < 8; ss++) s += red2[ss * 64 + c];
        mx[bh * 64 + c] = m;
        sm[bh * 64 + c] = s;
    }
}

// ---------------------------------------------------------------------------
__global__ void ktv_k(const float* __restrict__ Kh, const float* __restrict__ Vh,
                      const float* __restrict__ mx, const float* __restrict__ sm,
                      float* __restrict__ ktv)
{
    const int bh = blockIdx.y;
    const int chunk = blockIdx.x;
    const int tid = threadIdx.x;
    __shared__ float sk[4][64];
    __shared__ float sv[4][64];

    const float* kp = Kh + (long)bh * 4096 * 64;
    const float* vp = Vh + (long)bh * 4096 * 64;
    const int lc = tid & 63, lr = tid >> 6;
    const float lm = mx[bh * 64 + lc];
    const float lrs = 1.f / sm[bh * 64 + lc];

    const int i0 = (tid & 15) * 4;
    const int j0 = (tid >> 4) * 4;
    float acc[4][4] = {};

    const int nend = chunk * 512 + 512;
    for (int n0 = chunk * 512; n0 < nend; n0 += 4) {
        sk[lr][lc] = __expf(kp[(long)(n0 + lr) * 64 + lc] - lm) * lrs;
        sv[lr][lc] = vp[(long)(n0 + lr) * 64 + lc];
        __syncthreads();
#pragma unroll
        for (int r = 0; r < 4; r++) {
            float a[4], bv[4];
#pragma unroll
            for (int i = 0; i < 4; i++) a[i] = sk[r][i0 + i];
#pragma unroll
            for (int j = 0; j < 4; j++) bv[j] = sv[r][j0 + j];
#pragma unroll
            for (int i = 0; i < 4; i++)
#pragma unroll
                for (int j = 0; j < 4; j++) acc[i][j] = fmaf(a[i], bv[j], acc[i][j]);
        }
        __syncthreads();
    }
    float* kp2 = ktv + (long)bh * 4096;
#pragma unroll
    for (int i = 0; i < 4; i++)
#pragma unroll
        for (int j = 0; j < 4; j++)
            atomicAdd(&kp2[(i0 + i) * 64 + (j0 + j)], acc[i][j]);
}

// ---------------------------------------------------------------------------
__global__ void eff_k(const float* __restrict__ Qh, const float* __restrict__ ktv,
                      const float* __restrict__ crpe,
                      __nv_bfloat16* __restrict__ ohi, __nv_bfloat16* __restrict__ olo)
{
    const int bh = blockIdx.y;
    const int b = bh >> 3, h = bh & 7;
    const int n0 = blockIdx.x * 64;
    const int tid = threadIdx.x;

    __shared__ float skt[64][64];
    __shared__ float sq[64][65];

    const float* ktp = ktv + (long)bh * 4096;
    const float* qp  = Qh + ((long)bh * 4096 + n0) * 64;
    for (int i = tid; i < 4096; i += 256) {
        skt[i >> 6][i & 63] = ktp[i];
        sq[i >> 6][i & 63]  = qp[i];
    }
    __syncthreads();

    const int i0 = (tid & 15) * 4;
    const int j0 = (tid >> 4) * 4;
    float acc[4][4] = {};
#pragma unroll
    for (int c1 = 0; c1 < 64; c1++) {
        float a[4], bv[4];
#pragma unroll
        for (int i = 0; i < 4; i++) a[i] = sq[i0 + i][c1];
#pragma unroll
        for (int j = 0; j < 4; j++) bv[j] = skt[c1][j0 + j];
#pragma unroll
        for (int i = 0; i < 4; i++)
#pragma unroll
            for (int j = 0; j < 4; j++) acc[i][j] = fmaf(a[i], bv[j], acc[i][j]);
    }

    const float* crp = crpe + ((long)bh * 4096 + n0) * 64;
#pragma unroll
    for (int i = 0; i < 4; i++) {
        const int n = n0 + i0 + i;
        const long rbase = ((long)b * 4096 + n) * 640 + h * 64;
#pragma unroll
        for (int j = 0; j < 4; j++) {
            const int c2 = j0 + j;
            const float q = sq[i0 + i][c2];
            const float cr = q * crp[(long)(i0 + i) * 64 + c2];
            const float v = SCALE_V * acc[i][j] + cr;
            __nv_bfloat16 hh, ll;
            split_bf16(v, hh, ll);
            ohi[rbase + c2] = hh;
            olo[rbase + c2] = ll;
        }
    }
}

// ---------------------------------------------------------------------------
__global__ void ln2_k(const float* __restrict__ inQ, const float* __restrict__ inV,
                      const float* __restrict__ gQ, const float* __restrict__ bQ,
                      const float* __restrict__ gV, const float* __restrict__ bV,
                      __nv_bfloat16* __restrict__ ohi, __nv_bfloat16* __restrict__ olo)
{
    const int row  = blockIdx.x * 8 + (threadIdx.x >> 5);
    const int lane = threadIdx.x & 31;
    float4 vq = reinterpret_cast<const float4*>(inQ + (long)row * 128)[lane];
    float4 vv = reinterpret_cast<const float4*>(inV + (long)row * 128)[lane];

    float sQ = vq.x + vq.y + vq.z + vq.w;
    float qQ = vq.x * vq.x + vq.y * vq.y + vq.z * vq.z + vq.w * vq.w;
    float sV = vv.x + vv.y + vv.z + vv.w;
    float qV = vv.x * vv.x + vv.y * vv.y + vv.z * vv.z + vv.w * vv.w;
#pragma unroll
    for (int o = 16; o > 0; o >>= 1) {
        sQ += __shfl_xor_sync(0xffffffffu, sQ, o);
        qQ += __shfl_xor_sync(0xffffffffu, qQ, o);
        sV += __shfl_xor_sync(0xffffffffu, sV, o);
        qV += __shfl_xor_sync(0xffffffffu, qV, o);
    }
    const float mQ = sQ * (1.f / 128.f);
    const float rQ = rsqrtf(qQ * (1.f / 128.f) - mQ * mQ + LN_EPS);
    const float mV = sV * (1.f / 128.f);
    const float rV = rsqrtf(qV * (1.f / 128.f) - mV * mV + LN_EPS);

    const int c0 = lane * 4;
    const float aq[4] = {vq.x, vq.y, vq.z, vq.w};
    const float av[4] = {vv.x, vv.y, vv.z, vv.w};
    __nv_bfloat16 h[4], l[4];
#pragma unroll
    for (int i = 0; i < 4; i++) {
        float o1 = hsw((aq[i] - mQ) * rQ * gQ[c0 + i] + bQ[c0 + i]);
        float o2 = hsw((av[i] - mV) * rV * gV[c0 + i] + bV[c0 + i]);
        split_bf16(o1 + o2, h[i], l[i]);
    }
    const long ob = (long)row * 640 + 512 + c0;
    *reinterpret_cast<__nv_bfloat162*>(&ohi[ob])     = __nv_bfloat162(h[0], h[1]);
    *reinterpret_cast<__nv_bfloat162*>(&ohi[ob + 2]) = __nv_bfloat162(h[2], h[3]);
    *reinterpret_cast<__nv_bfloat162*>(&olo[ob])     = __nv_bfloat162(l[0], l[1]);
    *reinterpret_cast<__nv_bfloat162*>(&olo[ob + 2]) = __nv_bfloat162(l[2], l[3]);
}

// ---------------------------------------------------------------------------
extern "C" void kernel_launch(void* const* d_in, const int* in_sizes, int n_in,
                              void* d_out, int out_size)
{
    (void)in_sizes; (void)n_in; (void)out_size;
    const float* x        = (const float*)d_in[0];
    const float* y        = (const float*)d_in[1];
    const float* kv_w     = (const float*)d_in[2];
    const float* proj_w   = (const float*)d_in[3];
    const float* proj_b   = (const float*)d_in[4];
    const float* crpe_w3  = (const float*)d_in[5];
    const float* crpe_w5  = (const float*)d_in[6];
    const float* crpe_w7  = (const float*)d_in[7];
    const float* aq_dw3   = (const float*)d_in[8];
    const float* aq_dw5   = (const float*)d_in[9];
    const float* aq_dw7   = (const float*)d_in[10];
    const float* aq_pw    = (const float*)d_in[11];
    const float* aq_ln_g  = (const float*)d_in[12];
    const float* aq_ln_b  = (const float*)d_in[13];
    const float* aq_bn_g  = (const float*)d_in[14];
    const float* aq_bn_b  = (const float*)d_in[15];
    const float* akv_dw3  = (const float*)d_in[16];
    const float* akv_dw5  = (const float*)d_in[17];
    const float* akv_dw7  = (const float*)d_in[18];
    const float* akv_pw   = (const float*)d_in[19];
    const float* akv_ln_g = (const float*)d_in[20];
    const float* akv_ln_b = (const float*)d_in[21];
    const float* akv_bn_g = (const float*)d_in[22];
    const float* akv_bn_b = (const float*)d_in[23];

    float* sc = nullptr;
    cudaGetSymbolAddress((void**)&sc, g_scratch);
    float* kv      = sc;
    float* Qh      = sc + 41943040ULL;
    float* Kh      = sc + 58720256ULL;
    float* Vh      = sc + 75497472ULL;
    float* crpe    = sc + 92274688ULL;
    __nv_bfloat16* PQh = (__nv_bfloat16*)(sc + 109051904ULL);
    __nv_bfloat16* PQl = (__nv_bfloat16*)(sc + 109084672ULL);
    __nv_bfloat16* PKh = (__nv_bfloat16*)(sc + 109117440ULL);
    __nv_bfloat16* PKl = (__nv_bfloat16*)(sc + 109150208ULL);
    __nv_bfloat16* PWh = (__nv_bfloat16*)(sc + 109182976ULL);
    __nv_bfloat16* PWl = (__nv_bfloat16*)(sc + 109387776ULL);
    float* locrawQ = sc + 109592576ULL;
    float* locrawV = sc + 113786880ULL;
    float* mx      = sc + 117981184ULL;
    float* smv     = sc + 117985280ULL;
    float* ktv     = sc + 117989376ULL;
    __nv_bfloat16* Ahi = (__nv_bfloat16*)(sc + 118251520ULL);
    __nv_bfloat16* Alo = (__nv_bfloat16*)(sc + 128737280ULL);
    __nv_bfloat16* Whi = (__nv_bfloat16*)(sc + 139223040ULL);
    __nv_bfloat16* Wlo = (__nv_bfloat16*)(sc + 139632640ULL);
    __nv_bfloat16* Tb  = (__nv_bfloat16*)(sc + 140042240ULL);
    const long TS = 4194304L;
    // slots: 0 q3 | 1 q5 | 2 q7 | 3 qloc | 4 k (shared) | 5 v3 | 6 v5 | 7 v7 | 8 vloc
#define THI(i) (Tb + (long)(2 * (i)) * TS)
#define TLO(i) (Tb + (long)(2 * (i) + 1) * TS)

    cudaFuncSetAttribute(mgemm_k<0>, cudaFuncAttributeMaxDynamicSharedMemorySize, MG_SMEM);
    cudaFuncSetAttribute(mgemm_k<1>, cudaFuncAttributeMaxDynamicSharedMemorySize, MG_SMEM);
    cudaFuncSetAttribute(mgemm_k<2>, cudaFuncAttributeMaxDynamicSharedMemorySize, MG_SMEM);
    cudaFuncSetAttribute(mgemm_k<3>, cudaFuncAttributeMaxDynamicSharedMemorySize, MG_SMEM);

    static cudaStream_t sB = nullptr, sC = nullptr;
    static cudaEvent_t evFork, evK, evQ, evVh, evVloc, evV, evP1;
    if (sB == nullptr) {
        cudaStreamCreateWithFlags(&sB, cudaStreamNonBlocking);
        cudaStreamCreateWithFlags(&sC, cudaStreamNonBlocking);
        cudaEventCreateWithFlags(&evFork, cudaEventDisableTiming);
        cudaEventCreateWithFlags(&evK, cudaEventDisableTiming);
        cudaEventCreateWithFlags(&evQ, cudaEventDisableTiming);
        cudaEventCreateWithFlags(&evVh, cudaEventDisableTiming);
        cudaEventCreateWithFlags(&evVloc, cudaEventDisableTiming);
        cudaEventCreateWithFlags(&evV, cudaEventDisableTiming);
        cudaEventCreateWithFlags(&evP1, cudaEventDisableTiming);
    }

    const dim3 dwG(512, 8), dwB(32, 8);
    const long kvO = 4096L * 1280, yO = 4096L * 640, tO = 4096L * 128;

#define DW(st, KS, src, inRow, inO, wptr, slot)                                 \
    dwconv4_k<KS, 128, 1><<<dwG, dwB, 128 * KS * KS * 4, st>>>(                 \
        src, inO, 0, inRow, nullptr, THI(slot), TLO(slot), tO, 0, wptr, 1)
#define PC(st, slot, pwh, pwl, dst, bg, bb2, hb)                                \
    mgemm_k<2><<<dim3(1, 256), 256, MG_SMEM, st>>>(                             \
        THI(slot), TLO(slot), pwh, pwl, dst, 0, 128, 128, 128, bg, bb2, hb)

    cudaEventRecord(evFork, 0);
    cudaStreamWaitEvent(sB, evFork, 0);

    // ---- A: cvt + k-half GEMM (profiled slot #4) ----------------------------
    cvt_k<<<20480, 256>>>(x, Ahi, Alo, 20971520L);
    cvt_k<<<800, 256>>>(kv_w, Whi, Wlo, 819200L);
    cvt_k<<<64, 256>>>(akv_pw, PKh, PKl, 65536L);
    mgemm_k<0><<<dim3(5, 256), 256, MG_SMEM>>>(Ahi, Alo, Whi, Wlo, kv, 1280,
                                               640, 640, 640, nullptr, nullptr, 0);
    cudaEventRecord(evK, 0);

    // ---- sB: q-chain ---------------------------------------------------------
    cvt_k<<<64, 256, 0, sB>>>(aq_pw, PQh, PQl, 65536L);
    cvt_k<<<400, 256, 0, sB>>>(proj_w, PWh, PWl, 409600L);
    seg0_k<<<dim3(2048, 8), dim3(128, 2), 0, sB>>>(y, 640, Qh, aq_bn_g, aq_bn_b);
    DW(sB, 3, y + 128, 640, yO, aq_dw3 + 1152, 0);
    PC(sB, 0, PQh + 16384, PQl + 16384, Qh, aq_bn_g + 128, aq_bn_b + 128, 2);
    DW(sB, 5, y + 256, 640, yO, aq_dw5, 1);
    PC(sB, 1, PQh + 2 * 16384, PQl + 2 * 16384, Qh, aq_bn_g + 256, aq_bn_b + 256, 4);
    DW(sB, 7, y + 384, 640, yO, aq_dw7, 2);
    PC(sB, 2, PQh + 3 * 16384, PQl + 3 * 16384, Qh, aq_bn_g + 384, aq_bn_b + 384, 6);
    DW(sB, 3, y + 512, 640, yO, aq_dw3, 3);
    mgemm_k<0><<<dim3(1, 256), 256, MG_SMEM, sB>>>(THI(3), TLO(3), PQh, PQl,
                                                   locrawQ, 128, 128, 128, 128,
                                                   nullptr, nullptr, 0);
    cudaEventRecord(evQ, sB);

    // ---- sC: v-half GEMM + v-chain + vloc + crpe -----------------------------
    cudaStreamWaitEvent(sC, evK, 0);
    mgemm_k<0><<<dim3(5, 256), 256, MG_SMEM, sC>>>(Ahi, Alo,
                                                   Whi + 640L * 640, Wlo + 640L * 640,
                                                   kv + 640, 1280, 640, 640, 640,
                                                   nullptr, nullptr, 0);
    seg0_k<<<dim3(2048, 8), dim3(128, 2), 0, sC>>>(kv + 640, 1280, Vh,
                                                   akv_bn_g, akv_bn_b);
    DW(sC, 3, kv + 640 + 128, 1280, kvO, akv_dw3 + 1152, 5);
    PC(sC, 5, PKh + 16384, PKl + 16384, Vh, akv_bn_g + 128, akv_bn_b + 128, 2);
    DW(sC, 5, kv + 640 + 256, 1280, kvO, akv_dw5, 6);
    PC(sC, 6, PKh + 2 * 16384, PKl + 2 * 16384, Vh, akv_bn_g + 256, akv_bn_b + 256, 4);
    DW(sC, 7, kv + 640 + 384, 1280, kvO, akv_dw7, 7);
    PC(sC, 7, PKh + 3 * 16384, PKl + 3 * 16384, Vh, akv_bn_g + 384, akv_bn_b + 384, 6);
    cudaEventRecord(evVh, sC);                      // Vh complete
    DW(sC, 3, kv + 640 + 512, 1280, kvO, akv_dw3, 8);
    mgemm_k<0><<<dim3(1, 256), 256, MG_SMEM, sC>>>(THI(8), TLO(8), PKh, PKl,
                                                   locrawV, 128, 128, 128, 128,
                                                   nullptr, nullptr, 0);
    cudaEventRecord(evVloc, sC);
    {
        const long hs = 4096L * 64;
        dwconv4_k<3, 64, 0><<<dim3(512, 16), dim3(16, 8), 64 * 9 * 4, sC>>>(
            Vh, 8 * hs, hs, 64, crpe, nullptr, nullptr, 8 * hs, hs, crpe_w3, 2);
        dwconv4_k<5, 64, 0><<<dim3(512, 24), dim3(16, 8), 64 * 25 * 4, sC>>>(
            Vh + 2 * hs, 8 * hs, hs, 64, crpe + 2 * hs, nullptr, nullptr,
            8 * hs, hs, crpe_w5, 3);
        dwconv4_k<7, 64, 0><<<dim3(512, 24), dim3(16, 8), 64 * 49 * 4, sC>>>(
            Vh + 5 * hs, 8 * hs, hs, 64, crpe + 5 * hs, nullptr, nullptr,
            8 * hs, hs, crpe_w7, 3);
    }
    cudaEventRecord(evV, sC);

    // ---- A: k-chain + attention (starts right after kGEMM) -------------------
    seg0_k<<<dim3(2048, 8), dim3(128, 2)>>>(kv, 1280, Kh, akv_bn_g, akv_bn_b);
    DW(0, 3, kv + 128, 1280, kvO, akv_dw3 + 1152, 4);
    PC(0, 4, PKh + 16384, PKl + 16384, Kh, akv_bn_g + 128, akv_bn_b + 128, 2);
    DW(0, 5, kv + 256, 1280, kvO, akv_dw5, 4);
    PC(0, 4, PKh + 2 * 16384, PKl + 2 * 16384, Kh, akv_bn_g + 256, akv_bn_b + 256, 4);
    DW(0, 7, kv + 384, 1280, kvO, akv_dw7, 4);
    PC(0, 4, PKh + 3 * 16384, PKl + 3 * 16384, Kh, akv_bn_g + 384, akv_bn_b + 384, 6);
    softstats_k<<<64, 512>>>(Kh, mx, smv, ktv);
    cudaStreamWaitEvent(0, evVh, 0);
    ktv_k<<<dim3(8, 64), 256>>>(Kh, Vh, mx, smv, ktv);

    // ---- sB: ln2 + early proj slice (cols [512,640) of K) --------------------
    cudaStreamWaitEvent(sB, evVloc, 0);
    ln2_k<<<4096, 256, 0, sB>>>(locrawQ, locrawV, aq_ln_g, aq_ln_b,
                                akv_ln_g, akv_ln_b, Ahi, Alo);
    mgemm_k<1><<<dim3(5, 256), 256, MG_SMEM, sB>>>(Ahi + 512, Alo + 512,
                                                   PWh + 512, PWl + 512,
                                                   (float*)d_out, 640, 128, 640, 640,
                                                   nullptr, proj_b, 0);
    cudaEventRecord(evP1, sB);

    // ---- A: eff + late proj slice (cols [0,512), accumulate) -----------------
    cudaStreamWaitEvent(0, evV, 0);
    cudaStreamWaitEvent(0, evQ, 0);
    eff_k<<<dim3(64, 64), 256>>>(Qh, ktv, crpe, Ahi, Alo);
    cudaStreamWaitEvent(0, evP1, 0);
    mgemm_k<3><<<dim3(5, 256), 256, MG_SMEM>>>(Ahi, Alo, PWh, PWl,
                                               (float*)d_out, 640, 512, 640, 640,
                                               nullptr, nullptr, 0);
#undef DW
#undef PC
#undef THI
#undef TLO
}

// round 17
// speedup vs baseline: 1.0428x; 1.0428x over previous
#include <cuda_runtime.h>
#include <cuda_bf16.h>
#include <cstdint>

// ---------------------------------------------------------------------------
// CrossAtt for GB300 — round 17: round-15 base (fused kv GEMM) with the vloc
// branch moved to sB so crpe starts right after Vh and eff/proj shift earlier.
//  A : cvt -> kvGEMM(evKV) -> k-chain -> softstats -> [evVh] ktv ->
//      [evV,evQ] eff -> [evP1] proj[K 0:512] +=
//  sB: q-chain (evQ) -> qloc -> [evKV] vloc -> ln2 -> proj[K 512:640] -> evP1
//  sC: [evKV] v-chain (evVh) -> crpe -> evV
// ---------------------------------------------------------------------------

#define RSQ_BN 0.9999950000374997f
#define SCALE_V 0.11180339887498949f
#define LN_EPS 1e-5f

__device__ __forceinline__ float hsw(float x) {
    return x * fminf(fmaxf(x + 3.f, 0.f), 6.f) * (1.f / 6.f);
}

__device__ __forceinline__ uint32_t smem_u32(const void* p) {
    uint32_t a;
    asm("{ .reg .u64 t; cvta.to.shared.u64 t, %1; cvt.u32.u64 %0, t; }"
        : "=r"(a) : "l"(p));
    return a;
}
__device__ __forceinline__ void cp16(uint32_t s, const void* g) {
    asm volatile("cp.async.cg.shared.global [%0], [%1], 16;" :: "r"(s), "l"(g));
}
__device__ __forceinline__ void ldm_x4(uint32_t& r0, uint32_t& r1,
                                       uint32_t& r2, uint32_t& r3, uint32_t a) {
    asm volatile("ldmatrix.sync.aligned.m8n8.x4.shared.b16 {%0,%1,%2,%3}, [%4];"
        : "=r"(r0), "=r"(r1), "=r"(r2), "=r"(r3) : "r"(a));
}
__device__ __forceinline__ void mma_bf16(float* d, const uint32_t* a, const uint32_t* b) {
    asm volatile(
        "mma.sync.aligned.m16n8k16.row.col.f32.bf16.bf16.f32 "
        "{%0,%1,%2,%3},{%4,%5,%6,%7},{%8,%9},{%0,%1,%2,%3};"
        : "+f"(d[0]), "+f"(d[1]), "+f"(d[2]), "+f"(d[3])
        : "r"(a[0]), "r"(a[1]), "r"(a[2]), "r"(a[3]), "r"(b[0]), "r"(b[1]));
}
__device__ __forceinline__ void split_bf16(float v, __nv_bfloat16& h, __nv_bfloat16& l) {
    h = __float2bfloat16(v);
    l = __float2bfloat16(v - __bfloat162float(h));
}

// ---------------- scratch ----------------------------------------------------
static __device__ __align__(256) float g_scratch[186179584ULL];

// ---------------------------------------------------------------------------
__global__ void cvt_k(const float* __restrict__ s, __nv_bfloat16* __restrict__ hi,
                      __nv_bfloat16* __restrict__ lo, long n)
{
    long i = ((long)blockIdx.x * blockDim.x + threadIdx.x) * 4;
    if (i >= n) return;
    float4 v = *reinterpret_cast<const float4*>(s + i);
    float a[4] = {v.x, v.y, v.z, v.w};
    __nv_bfloat16 h[4], l[4];
#pragma unroll
    for (int j = 0; j < 4; j++) split_bf16(a[j], h[j], l[j]);
    *reinterpret_cast<__nv_bfloat162*>(hi + i)     = __nv_bfloat162(h[0], h[1]);
    *reinterpret_cast<__nv_bfloat162*>(hi + i + 2) = __nv_bfloat162(h[2], h[3]);
    *reinterpret_cast<__nv_bfloat162*>(lo + i)     = __nv_bfloat162(l[0], l[1]);
    *reinterpret_cast<__nv_bfloat162*>(lo + i + 2) = __nv_bfloat162(l[2], l[3]);
}

// ---------------------------------------------------------------------------
// MMA GEMM: 128x128 block, 8 warps, k16 stages, shared hi/lo tiles,
// 4-stage cp.async pipeline, 2 CTAs/SM. lda/ldb row strides (>= K).
// MODE 0: C=acc  1: C=acc+p2[n]  2: BN+hswish head-scatter  3: C+=acc
// ---------------------------------------------------------------------------
#define MG_SMEM 98304

template <int MODE>
__global__ void __launch_bounds__(256, 2) mgemm_k(
    const __nv_bfloat16* __restrict__ Ahi, const __nv_bfloat16* __restrict__ Alo,
    const __nv_bfloat16* __restrict__ Bhi, const __nv_bfloat16* __restrict__ Blo,
    float* __restrict__ C, int ldc, int K, int lda, int ldb,
    const float* __restrict__ p1, const float* __restrict__ p2, int headBase)
{
    extern __shared__ __align__(16) char smem[];
    const uint32_t sbase = smem_u32(smem);

    const int tid = threadIdx.x;
    const int wid = tid >> 5, lane = tid & 31;
    const int warp_m = wid >> 2, warp_n = wid & 3;
    const int m0 = blockIdx.y * 128, n0 = blockIdx.x * 128;

    const int SC = K >> 4;

    const int row = tid >> 1, half = tid & 1;
    const uint32_t soff = (uint32_t)(row * 48 + half * 16);
    const long aRow = (long)(m0 + row) * lda + half * 8;
    const long bRow = (long)(n0 + row) * ldb + half * 8;

    float acc[4][4][4] = {};

    const uint32_t aLdm = (uint32_t)((warp_m * 64 + (lane & 15)) * 48 + (lane >> 4) * 16);
    const uint32_t bLdm = (uint32_t)((warp_n * 32 + (lane & 15)) * 48 + (lane >> 4) * 16);

#define ST_BASE(st) (sbase + (uint32_t)(st) * 24576u)
#define ISSUE(s, st)                                                           \
    {                                                                          \
        const int ko = (s) << 4;                                               \
        const uint32_t sb = ST_BASE(st);                                       \
        cp16(sb + soff,          Ahi + aRow + ko);                             \
        cp16(sb + 6144u + soff,  Alo + aRow + ko);                             \
        cp16(sb + 12288u + soff, Bhi + bRow + ko);                             \
        cp16(sb + 18432u + soff, Blo + bRow + ko);                             \
        asm volatile("cp.async.commit_group;" ::: "memory");                   \
    }

    ISSUE(0, 0);
    ISSUE(1, 1);
    ISSUE(2, 2);

    for (int s = 0; s < SC; s++) {
        const int st = s & 3;
        if (s + 2 < SC) {
            asm volatile("cp.async.wait_group 2;" ::: "memory");
        } else if (s + 1 < SC) {
            asm volatile("cp.async.wait_group 1;" ::: "memory");
        } else {
            asm volatile("cp.async.wait_group 0;" ::: "memory");
        }
        __syncthreads();

        const uint32_t sb = ST_BASE(st);

        uint32_t bh[4][2], bl[4][2];
#pragma unroll
        for (int bi = 0; bi < 2; bi++) {
            uint32_t q0, q1, q2, q3;
            ldm_x4(q0, q1, q2, q3, sb + 12288u + bLdm + bi * 768u);
            bh[bi * 2 + 0][0] = q0; bh[bi * 2 + 0][1] = q2;
            bh[bi * 2 + 1][0] = q1; bh[bi * 2 + 1][1] = q3;
            ldm_x4(q0, q1, q2, q3, sb + 18432u + bLdm + bi * 768u);
            bl[bi * 2 + 0][0] = q0; bl[bi * 2 + 0][1] = q2;
            bl[bi * 2 + 1][0] = q1; bl[bi * 2 + 1][1] = q3;
        }
#pragma unroll
        for (int mf = 0; mf < 4; mf++) {
            uint32_t a[4];
            ldm_x4(a[0], a[1], a[2], a[3], sb + aLdm + mf * 768u);
#pragma unroll
            for (int nf = 0; nf < 4; nf++) {
                mma_bf16(acc[mf][nf], a, bh[nf]);
                mma_bf16(acc[mf][nf], a, bl[nf]);
            }
        }
#pragma unroll
        for (int mf = 0; mf < 4; mf++) {
            uint32_t a[4];
            ldm_x4(a[0], a[1], a[2], a[3], sb + 6144u + aLdm + mf * 768u);
#pragma unroll
            for (int nf = 0; nf < 4; nf++)
                mma_bf16(acc[mf][nf], a, bh[nf]);
        }
        if (s + 3 < SC) ISSUE(s + 3, (s + 3) & 3);
    }
#undef ISSUE
#undef ST_BASE

    const int lr = lane >> 2;
    const int lc = (lane & 3) * 2;
#pragma unroll
    for (int mf = 0; mf < 4; mf++) {
#pragma unroll
        for (int nf = 0; nf < 4; nf++) {
            const int n = n0 + warp_n * 32 + nf * 8 + lc;
#pragma unroll
            for (int h2 = 0; h2 < 2; h2++) {
                const int m = m0 + warp_m * 64 + mf * 16 + lr + h2 * 8;
                float v0 = acc[mf][nf][2 * h2 + 0];
                float v1 = acc[mf][nf][2 * h2 + 1];
                if (MODE == 0) {
                    *reinterpret_cast<float2*>(&C[(long)m * ldc + n]) =
                        make_float2(v0, v1);
                } else if (MODE == 1) {
                    *reinterpret_cast<float2*>(&C[(long)m * ldc + n]) =
                        make_float2(v0 + p2[n], v1 + p2[n + 1]);
                } else if (MODE == 3) {
                    float2 prev = *reinterpret_cast<const float2*>(&C[(long)m * ldc + n]);
                    *reinterpret_cast<float2*>(&C[(long)m * ldc + n]) =
                        make_float2(v0 + prev.x, v1 + prev.y);
                } else {
                    v0 = hsw(v0 * (p1[n] * RSQ_BN) + p2[n]);
                    v1 = hsw(v1 * (p1[n + 1] * RSQ_BN) + p2[n + 1]);
                    const int bb = m >> 12, nn = m & 4095;
                    const int hh = headBase + (n >> 6), cc = n & 63;
                    *reinterpret_cast<float2*>(
                        &C[((((long)bb * 8 + hh) * 4096) + nn) * 64 + cc]) =
                        make_float2(v0, v1);
                }
            }
        }
    }
}

// ---------------------------------------------------------------------------
__global__ void seg0_k(const float* __restrict__ in, int inRow,
                       float* __restrict__ hb,
                       const float* __restrict__ g, const float* __restrict__ bb)
{
    const int c = threadIdx.x;
    const int n = blockIdx.x * blockDim.y + threadIdx.y;
    const int b = blockIdx.y;
    float v = in[((long)b * 4096 + n) * (long)inRow + c];
    v = v * (g[c] * RSQ_BN) + bb[c];
    v = hsw(v);
    const int h = c >> 6, cc = c & 63;
    hb[(((long)b * 8 + h) * 4096 + n) * 64 + cc] = v;
}

// ---------------------------------------------------------------------------
template <int KS, int C, int BF>
__global__ void dwconv4_k(const float* __restrict__ in, long inOuter, long inInner,
                          int inRow,
                          float* __restrict__ out,
                          __nv_bfloat16* __restrict__ ohi, __nv_bfloat16* __restrict__ olo,
                          long outOuter, long outInner,
                          const float* __restrict__ w, int nh)
{
    extern __shared__ float ws[];
    const int batch = blockIdx.y;
    const int outer = batch / nh, inner = batch % nh;
    const float* ip = in + outer * inOuter + inner * inInner;
    const float* wp = w + (long)inner * C * KS * KS;

    const int nthr = blockDim.x * blockDim.y;
    const int tid = threadIdx.y * blockDim.x + threadIdx.x;
    for (int i = tid; i < C * KS * KS; i += nthr) {
        const int c = i / (KS * KS);
        const int t = i - c * (KS * KS);
        ws[t * C + c] = wp[i];
    }
    __syncthreads();

    const int c0 = threadIdx.x * 4;
    const int pix = blockIdx.x * blockDim.y + threadIdx.y;
    const int y = pix >> 6, x = pix & 63;
    const int P = KS / 2;
    float4 acc = make_float4(0.f, 0.f, 0.f, 0.f);
#pragma unroll
    for (int dy = 0; dy < KS; dy++) {
        const int yy = y + dy - P;
        if (yy < 0 || yy > 63) continue;
#pragma unroll
        for (int dx = 0; dx < KS; dx++) {
            const int xx = x + dx - P;
            if (xx < 0 || xx > 63) continue;
            const float4 wv = *reinterpret_cast<const float4*>(
                &ws[(dy * KS + dx) * C + c0]);
            const float4 iv = *reinterpret_cast<const float4*>(
                &ip[(long)(yy * 64 + xx) * inRow + c0]);
            acc.x = fmaf(wv.x, iv.x, acc.x);
            acc.y = fmaf(wv.y, iv.y, acc.y);
            acc.z = fmaf(wv.z, iv.z, acc.z);
            acc.w = fmaf(wv.w, iv.w, acc.w);
        }
    }
    const long obase = outer * outOuter + inner * outInner + (long)pix * C + c0;
    if (BF == 0) {
        *reinterpret_cast<float4*>(&out[obase]) = acc;
    } else {
        float a[4] = {acc.x, acc.y, acc.z, acc.w};
        __nv_bfloat16 h[4], l[4];
#pragma unroll
        for (int i = 0; i < 4; i++) split_bf16(a[i], h[i], l[i]);
        *reinterpret_cast<__nv_bfloat162*>(&ohi[obase])     = __nv_bfloat162(h[0], h[1]);
        *reinterpret_cast<__nv_bfloat162*>(&ohi[obase + 2]) = __nv_bfloat162(h[2], h[3]);
        *reinterpret_cast<__nv_bfloat162*>(&olo[obase])     = __nv_bfloat162(l[0], l[1]);
        *reinterpret_cast<__nv_bfloat162*>(&olo[obase + 2]) = __nv_bfloat162(l[2], l[3]);
    }
}

// ---------------------------------------------------------------------------
__global__ void softstats_k(const float* __restrict__ Kh,
                            float* __restrict__ mx, float* __restrict__ sm,
                            float* __restrict__ ktv)
{
    const int bh = blockIdx.x;
    const int c  = threadIdx.x & 63;
    const int sl = threadIdx.x >> 6;
    const float* kp = Kh + (long)bh * 4096 * 64;

    float* kz = ktv + (long)bh * 4096;
    for (int i = threadIdx.x; i < 4096; i += 512) kz[i] = 0.f;

    float m = -1e30f;
    for (int j = 0; j < 512; j++) {
        const int n = sl * 512 + j;
        m = fmaxf(m, kp[(long)n * 64 + c]);
    }
    __shared__ float red[512];
    __shared__ float red2[512];
    red[threadIdx.x] = m;
    __syncthreads();
    if (sl == 0) {
        for (int s = 1; s < 8; s++) m = fmaxf(m, red[s * 64 + c]);
        red[c] = m;
    }
    __syncthreads();
    m = red[c];

    float s = 0.f;
    for (int j = 0; j < 512; j++) {
        const int n = sl * 512 + j;
        s += __expf(kp[(long)n * 64 + c] - m);
    }
    red2[threadIdx.x] = s;
    __syncthreads();
    if (sl == 0) {
        for (int ss = 1; ss < 8; ss++) s += red2[ss * 64 + c];
        mx[bh * 64 + c] = m;
        sm[bh * 64 + c] = s;
    }
}

// ---------------------------------------------------------------------------
__global__ void ktv_k(const float* __restrict__ Kh, const float* __restrict__ Vh,
                      const float* __restrict__ mx, const float* __restrict__ sm,
                      float* __restrict__ ktv)
{
    const int bh = blockIdx.y;
    const int chunk = blockIdx.x;
    const int tid = threadIdx.x;
    __shared__ float sk[4][64];
    __shared__ float sv[4][64];

    const float* kp = Kh + (long)bh * 4096 * 64;
    const float* vp = Vh + (long)bh * 4096 * 64;
    const int lc = tid & 63, lr = tid >> 6;
    const float lm = mx[bh * 64 + lc];
    const float lrs = 1.f / sm[bh * 64 + lc];

    const int i0 = (tid & 15) * 4;
    const int j0 = (tid >> 4) * 4;
    float acc[4][4] = {};

    const int nend = chunk * 512 + 512;
    for (int n0 = chunk * 512; n0 < nend; n0 += 4) {
        sk[lr][lc] = __expf(kp[(long)(n0 + lr) * 64 + lc] - lm) * lrs;
        sv[lr][lc] = vp[(long)(n0 + lr) * 64 + lc];
        __syncthreads();
#pragma unroll
        for (int r = 0; r < 4; r++) {
            float a[4], bv[4];
#pragma unroll
            for (int i = 0; i < 4; i++) a[i] = sk[r][i0 + i];
#pragma unroll
            for (int j = 0; j < 4; j++) bv[j] = sv[r][j0 + j];
#pragma unroll
            for (int i = 0; i < 4; i++)
#pragma unroll
                for (int j = 0; j < 4; j++) acc[i][j] = fmaf(a[i], bv[j], acc[i][j]);
        }
        __syncthreads();
    }
    float* kp2 = ktv + (long)bh * 4096;
#pragma unroll
    for (int i = 0; i < 4; i++)
#pragma unroll
        for (int j = 0; j < 4; j++)
            atomicAdd(&kp2[(i0 + i) * 64 + (j0 + j)], acc[i][j]);
}

// ---------------------------------------------------------------------------
__global__ void eff_k(const float* __restrict__ Qh, const float* __restrict__ ktv,
                      const float* __restrict__ crpe,
                      __nv_bfloat16* __restrict__ ohi, __nv_bfloat16* __restrict__ olo)
{
    const int bh = blockIdx.y;
    const int b = bh >> 3, h = bh & 7;
    const int n0 = blockIdx.x * 64;
    const int tid = threadIdx.x;

    __shared__ float skt[64][64];
    __shared__ float sq[64][65];

    const float* ktp = ktv + (long)bh * 4096;
    const float* qp  = Qh + ((long)bh * 4096 + n0) * 64;
    for (int i = tid; i < 4096; i += 256) {
        skt[i >> 6][i & 63] = ktp[i];
        sq[i >> 6][i & 63]  = qp[i];
    }
    __syncthreads();

    const int i0 = (tid & 15) * 4;
    const int j0 = (tid >> 4) * 4;
    float acc[4][4] = {};
#pragma unroll
    for (int c1 = 0; c1 < 64; c1++) {
        float a[4], bv[4];
#pragma unroll
        for (int i = 0; i < 4; i++) a[i] = sq[i0 + i][c1];
#pragma unroll
        for (int j = 0; j < 4; j++) bv[j] = skt[c1][j0 + j];
#pragma unroll
        for (int i = 0; i < 4; i++)
#pragma unroll
            for (int j = 0; j < 4; j++) acc[i][j] = fmaf(a[i], bv[j], acc[i][j]);
    }

    const float* crp = crpe + ((long)bh * 4096 + n0) * 64;
#pragma unroll
    for (int i = 0; i < 4; i++) {
        const int n = n0 + i0 + i;
        const long rbase = ((long)b * 4096 + n) * 640 + h * 64;
#pragma unroll
        for (int j = 0; j < 4; j++) {
            const int c2 = j0 + j;
            const float q = sq[i0 + i][c2];
            const float cr = q * crp[(long)(i0 + i) * 64 + c2];
            const float v = SCALE_V * acc[i][j] + cr;
            __nv_bfloat16 hh, ll;
            split_bf16(v, hh, ll);
            ohi[rbase + c2] = hh;
            olo[rbase + c2] = ll;
        }
    }
}

// ---------------------------------------------------------------------------
__global__ void ln2_k(const float* __restrict__ inQ, const float* __restrict__ inV,
                      const float* __restrict__ gQ, const float* __restrict__ bQ,
                      const float* __restrict__ gV, const float* __restrict__ bV,
                      __nv_bfloat16* __restrict__ ohi, __nv_bfloat16* __restrict__ olo)
{
    const int row  = blockIdx.x * 8 + (threadIdx.x >> 5);
    const int lane = threadIdx.x & 31;
    float4 vq = reinterpret_cast<const float4*>(inQ + (long)row * 128)[lane];
    float4 vv = reinterpret_cast<const float4*>(inV + (long)row * 128)[lane];

    float sQ = vq.x + vq.y + vq.z + vq.w;
    float qQ = vq.x * vq.x + vq.y * vq.y + vq.z * vq.z + vq.w * vq.w;
    float sV = vv.x + vv.y + vv.z + vv.w;
    float qV = vv.x * vv.x + vv.y * vv.y + vv.z * vv.z + vv.w * vv.w;
#pragma unroll
    for (int o = 16; o > 0; o >>= 1) {
        sQ += __shfl_xor_sync(0xffffffffu, sQ, o);
        qQ += __shfl_xor_sync(0xffffffffu, qQ, o);
        sV += __shfl_xor_sync(0xffffffffu, sV, o);
        qV += __shfl_xor_sync(0xffffffffu, qV, o);
    }
    const float mQ = sQ * (1.f / 128.f);
    const float rQ = rsqrtf(qQ * (1.f / 128.f) - mQ * mQ + LN_EPS);
    const float mV = sV * (1.f / 128.f);
    const float rV = rsqrtf(qV * (1.f / 128.f) - mV * mV + LN_EPS);

    const int c0 = lane * 4;
    const float aq[4] = {vq.x, vq.y, vq.z, vq.w};
    const float av[4] = {vv.x, vv.y, vv.z, vv.w};
    __nv_bfloat16 h[4], l[4];
#pragma unroll
    for (int i = 0; i < 4; i++) {
        float o1 = hsw((aq[i] - mQ) * rQ * gQ[c0 + i] + bQ[c0 + i]);
        float o2 = hsw((av[i] - mV) * rV * gV[c0 + i] + bV[c0 + i]);
        split_bf16(o1 + o2, h[i], l[i]);
    }
    const long ob = (long)row * 640 + 512 + c0;
    *reinterpret_cast<__nv_bfloat162*>(&ohi[ob])     = __nv_bfloat162(h[0], h[1]);
    *reinterpret_cast<__nv_bfloat162*>(&ohi[ob + 2]) = __nv_bfloat162(h[2], h[3]);
    *reinterpret_cast<__nv_bfloat162*>(&olo[ob])     = __nv_bfloat162(l[0], l[1]);
    *reinterpret_cast<__nv_bfloat162*>(&olo[ob + 2]) = __nv_bfloat162(l[2], l[3]);
}

// ---------------------------------------------------------------------------
extern "C" void kernel_launch(void* const* d_in, const int* in_sizes, int n_in,
                              void* d_out, int out_size)
{
    (void)in_sizes; (void)n_in; (void)out_size;
    const float* x        = (const float*)d_in[0];
    const float* y        = (const float*)d_in[1];
    const float* kv_w     = (const float*)d_in[2];
    const float* proj_w   = (const float*)d_in[3];
    const float* proj_b   = (const float*)d_in[4];
    const float* crpe_w3  = (const float*)d_in[5];
    const float* crpe_w5  = (const float*)d_in[6];
    const float* crpe_w7  = (const float*)d_in[7];
    const float* aq_dw3   = (const float*)d_in[8];
    const float* aq_dw5   = (const float*)d_in[9];
    const float* aq_dw7   = (const float*)d_in[10];
    const float* aq_pw    = (const float*)d_in[11];
    const float* aq_ln_g  = (const float*)d_in[12];
    const float* aq_ln_b  = (const float*)d_in[13];
    const float* aq_bn_g  = (const float*)d_in[14];
    const float* aq_bn_b  = (const float*)d_in[15];
    const float* akv_dw3  = (const float*)d_in[16];
    const float* akv_dw5  = (const float*)d_in[17];
    const float* akv_dw7  = (const float*)d_in[18];
    const float* akv_pw   = (const float*)d_in[19];
    const float* akv_ln_g = (const float*)d_in[20];
    const float* akv_ln_b = (const float*)d_in[21];
    const float* akv_bn_g = (const float*)d_in[22];
    const float* akv_bn_b = (const float*)d_in[23];

    float* sc = nullptr;
    cudaGetSymbolAddress((void**)&sc, g_scratch);
    float* kv      = sc;
    float* Qh      = sc + 41943040ULL;
    float* Kh      = sc + 58720256ULL;
    float* Vh      = sc + 75497472ULL;
    float* crpe    = sc + 92274688ULL;
    __nv_bfloat16* PQh = (__nv_bfloat16*)(sc + 109051904ULL);
    __nv_bfloat16* PQl = (__nv_bfloat16*)(sc + 109084672ULL);
    __nv_bfloat16* PKh = (__nv_bfloat16*)(sc + 109117440ULL);
    __nv_bfloat16* PKl = (__nv_bfloat16*)(sc + 109150208ULL);
    __nv_bfloat16* PWh = (__nv_bfloat16*)(sc + 109182976ULL);
    __nv_bfloat16* PWl = (__nv_bfloat16*)(sc + 109387776ULL);
    float* locrawQ = sc + 109592576ULL;
    float* locrawV = sc + 113786880ULL;
    float* mx      = sc + 117981184ULL;
    float* smv     = sc + 117985280ULL;
    float* ktv     = sc + 117989376ULL;
    __nv_bfloat16* Ahi = (__nv_bfloat16*)(sc + 118251520ULL);
    __nv_bfloat16* Alo = (__nv_bfloat16*)(sc + 128737280ULL);
    __nv_bfloat16* Whi = (__nv_bfloat16*)(sc + 139223040ULL);
    __nv_bfloat16* Wlo = (__nv_bfloat16*)(sc + 139632640ULL);
    __nv_bfloat16* Tb  = (__nv_bfloat16*)(sc + 140042240ULL);
    const long TS = 4194304L;
    // slots: 0 q3 | 1 q5 | 2 q7 | 3 qloc | 4 k (shared) | 5 v3 | 6 v5 | 7 v7 | 8 vloc
#define THI(i) (Tb + (long)(2 * (i)) * TS)
#define TLO(i) (Tb + (long)(2 * (i) + 1) * TS)

    cudaFuncSetAttribute(mgemm_k<0>, cudaFuncAttributeMaxDynamicSharedMemorySize, MG_SMEM);
    cudaFuncSetAttribute(mgemm_k<1>, cudaFuncAttributeMaxDynamicSharedMemorySize, MG_SMEM);
    cudaFuncSetAttribute(mgemm_k<2>, cudaFuncAttributeMaxDynamicSharedMemorySize, MG_SMEM);
    cudaFuncSetAttribute(mgemm_k<3>, cudaFuncAttributeMaxDynamicSharedMemorySize, MG_SMEM);

    static cudaStream_t sB = nullptr, sC = nullptr;
    static cudaEvent_t evFork, evKV, evQ, evVh, evV, evP1;
    if (sB == nullptr) {
        cudaStreamCreateWithFlags(&sB, cudaStreamNonBlocking);
        cudaStreamCreateWithFlags(&sC, cudaStreamNonBlocking);
        cudaEventCreateWithFlags(&evFork, cudaEventDisableTiming);
        cudaEventCreateWithFlags(&evKV, cudaEventDisableTiming);
        cudaEventCreateWithFlags(&evQ, cudaEventDisableTiming);
        cudaEventCreateWithFlags(&evVh, cudaEventDisableTiming);
        cudaEventCreateWithFlags(&evV, cudaEventDisableTiming);
        cudaEventCreateWithFlags(&evP1, cudaEventDisableTiming);
    }

    const dim3 dwG(512, 8), dwB(32, 8);
    const long kvO = 4096L * 1280, yO = 4096L * 640, tO = 4096L * 128;

#define DW(st, KS, src, inRow, inO, wptr, slot)                                 \
    dwconv4_k<KS, 128, 1><<<dwG, dwB, 128 * KS * KS * 4, st>>>(                 \
        src, inO, 0, inRow, nullptr, THI(slot), TLO(slot), tO, 0, wptr, 1)
#define PC(st, slot, pwh, pwl, dst, bg, bb2, hb)                                \
    mgemm_k<2><<<dim3(1, 256), 256, MG_SMEM, st>>>(                             \
        THI(slot), TLO(slot), pwh, pwl, dst, 0, 128, 128, 128, bg, bb2, hb)

    cudaEventRecord(evFork, 0);
    cudaStreamWaitEvent(sB, evFork, 0);

    // ---- A: cvt + fused kv GEMM (profiled slot #4) --------------------------
    cvt_k<<<20480, 256>>>(x, Ahi, Alo, 20971520L);
    cvt_k<<<800, 256>>>(kv_w, Whi, Wlo, 819200L);
    cvt_k<<<64, 256>>>(akv_pw, PKh, PKl, 65536L);
    mgemm_k<0><<<dim3(10, 256), 256, MG_SMEM>>>(Ahi, Alo, Whi, Wlo, kv, 1280,
                                                640, 640, 640, nullptr, nullptr, 0);
    cudaEventRecord(evKV, 0);

    // ---- sB: q-chain + qloc, then vloc (after evKV), ln2, early proj --------
    cvt_k<<<64, 256, 0, sB>>>(aq_pw, PQh, PQl, 65536L);
    cvt_k<<<400, 256, 0, sB>>>(proj_w, PWh, PWl, 409600L);
    seg0_k<<<dim3(2048, 8), dim3(128, 2), 0, sB>>>(y, 640, Qh, aq_bn_g, aq_bn_b);
    DW(sB, 3, y + 128, 640, yO, aq_dw3 + 1152, 0);
    PC(sB, 0, PQh + 16384, PQl + 16384, Qh, aq_bn_g + 128, aq_bn_b + 128, 2);
    DW(sB, 5, y + 256, 640, yO, aq_dw5, 1);
    PC(sB, 1, PQh + 2 * 16384, PQl + 2 * 16384, Qh, aq_bn_g + 256, aq_bn_b + 256, 4);
    DW(sB, 7, y + 384, 640, yO, aq_dw7, 2);
    PC(sB, 2, PQh + 3 * 16384, PQl + 3 * 16384, Qh, aq_bn_g + 384, aq_bn_b + 384, 6);
    cudaEventRecord(evQ, sB);          // Qh complete
    DW(sB, 3, y + 512, 640, yO, aq_dw3, 3);
    mgemm_k<0><<<dim3(1, 256), 256, MG_SMEM, sB>>>(THI(3), TLO(3), PQh, PQl,
                                                   locrawQ, 128, 128, 128, 128,
                                                   nullptr, nullptr, 0);
    // vloc branch moved here (needs kv v-half)
    cudaStreamWaitEvent(sB, evKV, 0);
    DW(sB, 3, kv + 640 + 512, 1280, kvO, akv_dw3, 8);
    mgemm_k<0><<<dim3(1, 256), 256, MG_SMEM, sB>>>(THI(8), TLO(8), PKh, PKl,
                                                   locrawV, 128, 128, 128, 128,
                                                   nullptr, nullptr, 0);
    ln2_k<<<4096, 256, 0, sB>>>(locrawQ, locrawV, aq_ln_g, aq_ln_b,
                                akv_ln_g, akv_ln_b, Ahi, Alo);
    mgemm_k<1><<<dim3(5, 256), 256, MG_SMEM, sB>>>(Ahi + 512, Alo + 512,
                                                   PWh + 512, PWl + 512,
                                                   (float*)d_out, 640, 128, 640, 640,
                                                   nullptr, proj_b, 0);
    cudaEventRecord(evP1, sB);

    // ---- sC: v-chain (head branches) -> crpe ---------------------------------
    cudaStreamWaitEvent(sC, evKV, 0);
    seg0_k<<<dim3(2048, 8), dim3(128, 2), 0, sC>>>(kv + 640, 1280, Vh,
                                                   akv_bn_g, akv_bn_b);
    DW(sC, 3, kv + 640 + 128, 1280, kvO, akv_dw3 + 1152, 5);
    PC(sC, 5, PKh + 16384, PKl + 16384, Vh, akv_bn_g + 128, akv_bn_b + 128, 2);
    DW(sC, 5, kv + 640 + 256, 1280, kvO, akv_dw5, 6);
    PC(sC, 6, PKh + 2 * 16384, PKl + 2 * 16384, Vh, akv_bn_g + 256, akv_bn_b + 256, 4);
    DW(sC, 7, kv + 640 + 384, 1280, kvO, akv_dw7, 7);
    PC(sC, 7, PKh + 3 * 16384, PKl + 3 * 16384, Vh, akv_bn_g + 384, akv_bn_b + 384, 6);
    cudaEventRecord(evVh, sC);                      // Vh complete
    {
        const long hs = 4096L * 64;
        dwconv4_k<3, 64, 0><<<dim3(512, 16), dim3(16, 8), 64 * 9 * 4, sC>>>(
            Vh, 8 * hs, hs, 64, crpe, nullptr, nullptr, 8 * hs, hs, crpe_w3, 2);
        dwconv4_k<5, 64, 0><<<dim3(512, 24), dim3(16, 8), 64 * 25 * 4, sC>>>(
            Vh + 2 * hs, 8 * hs, hs, 64, crpe + 2 * hs, nullptr, nullptr,
            8 * hs, hs, crpe_w5, 3);
        dwconv4_k<7, 64, 0><<<dim3(512, 24), dim3(16, 8), 64 * 49 * 4, sC>>>(
            Vh + 5 * hs, 8 * hs, hs, 64, crpe + 5 * hs, nullptr, nullptr,
            8 * hs, hs, crpe_w7, 3);
    }
    cudaEventRecord(evV, sC);

    // ---- A: k-chain + attention ----------------------------------------------
    seg0_k<<<dim3(2048, 8), dim3(128, 2)>>>(kv, 1280, Kh, akv_bn_g, akv_bn_b);
    DW(0, 3, kv + 128, 1280, kvO, akv_dw3 + 1152, 4);
    PC(0, 4, PKh + 16384, PKl + 16384, Kh, akv_bn_g + 128, akv_bn_b + 128, 2);
    DW(0, 5, kv + 256, 1280, kvO, akv_dw5, 4);
    PC(0, 4, PKh + 2 * 16384, PKl + 2 * 16384, Kh, akv_bn_g + 256, akv_bn_b + 256, 4);
    DW(0, 7, kv + 384, 1280, kvO, akv_dw7, 4);
    PC(0, 4, PKh + 3 * 16384, PKl + 3 * 16384, Kh, akv_bn_g + 384, akv_bn_b + 384, 6);
    softstats_k<<<64, 512>>>(Kh, mx, smv, ktv);
    cudaStreamWaitEvent(0, evVh, 0);
    ktv_k<<<dim3(8, 64), 256>>>(Kh, Vh, mx, smv, ktv);

    // ---- A: eff + late proj slice (cols [0,512), accumulate) -----------------
    cudaStreamWaitEvent(0, evV, 0);
    cudaStreamWaitEvent(0, evQ, 0);
    eff_k<<<dim3(64, 64), 256>>>(Qh, ktv, crpe, Ahi, Alo);
    cudaStreamWaitEvent(0, evP1, 0);
    mgemm_k<3><<<dim3(5, 256), 256, MG_SMEM>>>(Ahi, Alo, PWh, PWl,
                                               (float*)d_out, 640, 512, 640, 640,
                                               nullptr, nullptr, 0);
#undef DW
#undef PC
#undef THI
#undef TLO
}